// round 15
// baseline (speedup 1.0000x reference)
#include <cuda_runtime.h>
#include <math.h>
#include <stdint.h>

// ---------------- dimensions ----------------
#define BB   2
#define TT   1024
#define CC   768
#define NH   12
#define HD   64
#define LL   4
#define VV   50257
#define NPAD 50304         // 393 * 128, head_w padded columns
#define NTOK 2048          // BB*TT
#define BH   24            // BB*NH

// weight-rounding buffer offsets (floats)
#define WQKV_SZ  ((size_t)LL * CC * 3 * CC)
#define WPROJ_SZ ((size_t)LL * CC * CC)
#define WFC_SZ   ((size_t)LL * CC * 4 * CC)
#define WFC2_SZ  ((size_t)LL * 4 * CC * CC)
#define OFF_QKV  0
#define OFF_PROJ (OFF_QKV + WQKV_SZ)
#define OFF_FC   (OFF_PROJ + WPROJ_SZ)
#define OFF_FC2  (OFF_FC + WFC_SZ)
#define WR_TOTAL (OFF_FC2 + WFC2_SZ)

// ---------------- scratch (static device globals; no allocs) ----------------
__device__ float g_x  [NTOK * CC];
__device__ float g_h  [NTOK * CC];
__device__ float g_qkv[NTOK * 3 * CC];
__device__ float g_y  [NTOK * CC];
__device__ float g_m1 [NTOK * 4 * CC];
__device__ float g_wpad[(size_t)CC * NPAD];   // padded+rounded head weights [CC][NPAD]
__device__ float g_wr [WR_TOTAL];             // tf32-rounded layer weights [K][N]

// ---------------- helpers ----------------
__device__ __forceinline__ float warpReduceSum(float v) {
    #pragma unroll
    for (int o = 16; o > 0; o >>= 1) v += __shfl_xor_sync(0xffffffffu, v, o);
    return v;
}
__device__ float blockReduceSum(float v) {
    __shared__ float s[32];
    int lane = threadIdx.x & 31, wid = threadIdx.x >> 5;
    v = warpReduceSum(v);
    if (lane == 0) s[wid] = v;
    __syncthreads();
    int nw = blockDim.x >> 5;
    v = (threadIdx.x < nw) ? s[threadIdx.x] : 0.f;
    if (wid == 0) v = warpReduceSum(v);
    if (threadIdx.x == 0) s[0] = v;
    __syncthreads();
    v = s[0];
    __syncthreads();
    return v;
}

__device__ __forceinline__ float gelu_f(float x) {
    const float k = 0.7978845608028654f;  // sqrt(2/pi)
    float x3 = x * x * x;
    return 0.5f * x * (1.f + tanhf(k * (x + 0.044715f * x3)));
}

__device__ __forceinline__ uint32_t f2tf32(float x) {
    uint32_t r;
    asm("cvt.rna.tf32.f32 %0, %1;" : "=r"(r) : "f"(x));
    return r;
}
__device__ __forceinline__ float roundtf(float x) {
    return __uint_as_float(f2tf32(x));
}

__device__ __forceinline__ void mma_tf32(float c[4],
                                         uint32_t a0, uint32_t a1, uint32_t a2, uint32_t a3,
                                         uint32_t b0, uint32_t b1) {
    asm volatile(
        "mma.sync.aligned.m16n8k8.row.col.f32.tf32.tf32.f32 "
        "{%0,%1,%2,%3}, {%4,%5,%6,%7}, {%8,%9}, {%0,%1,%2,%3};\n"
        : "+f"(c[0]), "+f"(c[1]), "+f"(c[2]), "+f"(c[3])
        : "r"(a0), "r"(a1), "r"(a2), "r"(a3), "r"(b0), "r"(b1));
}

__device__ __forceinline__ void ldsm4(uint32_t r[4], uint32_t addr) {
    asm volatile("ldmatrix.sync.aligned.m8n8.x4.shared.b16 {%0,%1,%2,%3}, [%4];"
        : "=r"(r[0]), "=r"(r[1]), "=r"(r[2]), "=r"(r[3]) : "r"(addr));
}

// ---------------- cp.async helpers ----------------
__device__ __forceinline__ void cp16(uint32_t dst, const void* src) {
    asm volatile("cp.async.cg.shared.global [%0], [%1], 16;" :: "r"(dst), "l"(src));
}
__device__ __forceinline__ void cp_commit() {
    asm volatile("cp.async.commit_group;");
}
__device__ __forceinline__ void cp_wait1() {
    asm volatile("cp.async.wait_group 1;");
}
__device__ __forceinline__ void cp_wait0() {
    asm volatile("cp.async.wait_group 0;");
}

// ---------------- fused prep: round all layer weights + pad/round head ----------------
#define P_S0 (WQKV_SZ / 4)
#define P_S1 (P_S0 + WPROJ_SZ / 4)
#define P_S2 (P_S1 + WFC_SZ / 4)
#define P_S3 (P_S2 + WFC2_SZ / 4)
#define P_S4 (P_S3 + ((size_t)CC * NPAD) / 4)

__global__ void prep_k(const float* __restrict__ qkv_w, const float* __restrict__ proj_w,
                       const float* __restrict__ fc_w, const float* __restrict__ fc2_w,
                       const float* __restrict__ head_w,
                       float* __restrict__ wr, float* __restrict__ wpad) {
    size_t i = (size_t)blockIdx.x * blockDim.x + threadIdx.x;
    if (i >= P_S4) return;
    if (i < P_S3) {
        const float* src;
        float* dst;
        size_t j;
        if (i < P_S0)      { src = qkv_w;  dst = wr + OFF_QKV;  j = i; }
        else if (i < P_S1) { src = proj_w; dst = wr + OFF_PROJ; j = i - P_S0; }
        else if (i < P_S2) { src = fc_w;   dst = wr + OFF_FC;   j = i - P_S1; }
        else               { src = fc2_w;  dst = wr + OFF_FC2;  j = i - P_S2; }
        float4 v = ((const float4*)src)[j];
        v.x = roundtf(v.x); v.y = roundtf(v.y);
        v.z = roundtf(v.z); v.w = roundtf(v.w);
        ((float4*)dst)[j] = v;
    } else {
        size_t base = (i - P_S3) * 4;
        int r = (int)(base / NPAD);
        int c = (int)(base % NPAD);
        const float* src = head_w + (size_t)r * VV;
        float4 v;
        v.x = (c + 0 < VV) ? roundtf(src[c + 0]) : 0.f;
        v.y = (c + 1 < VV) ? roundtf(src[c + 1]) : 0.f;
        v.z = (c + 2 < VV) ? roundtf(src[c + 2]) : 0.f;
        v.w = (c + 3 < VV) ? roundtf(src[c + 3]) : 0.f;
        *(float4*)&wpad[base] = v;
    }
}

// ---------------- embedding ----------------
__global__ void embed_k(const int* __restrict__ idx, const float* __restrict__ wte,
                        const float* __restrict__ wpe, float* __restrict__ x) {
    int row = blockIdx.x;              // b*TT + t
    int t = row & (TT - 1);
    int tok = idx[row];
    const float* we = wte + (size_t)tok * CC;
    const float* pe = wpe + (size_t)t * CC;
    float* o = x + (size_t)row * CC;
    for (int c = threadIdx.x; c < CC; c += blockDim.x) o[c] = we[c] + pe[c];
}

// ---------------- layernorm (output tf32-rounded: feeds GEMM A-side) ----------------
__global__ void layernorm_k(const float* __restrict__ in, const float* __restrict__ w,
                            const float* __restrict__ b, float* __restrict__ out) {
    int row = blockIdx.x;
    const float* p = in + (size_t)row * CC;
    int tid = threadIdx.x;
    float v[3];
    float s = 0.f;
    #pragma unroll
    for (int i = 0; i < 3; i++) { v[i] = p[tid + i * 256]; s += v[i]; }
    float mean = blockReduceSum(s) * (1.f / (float)CC);
    float vs = 0.f;
    #pragma unroll
    for (int i = 0; i < 3; i++) { float d = v[i] - mean; vs += d * d; }
    float var = blockReduceSum(vs) * (1.f / (float)CC);
    float rstd = rsqrtf(var + 1e-5f);
    float* o = out + (size_t)row * CC;
    #pragma unroll
    for (int i = 0; i < 3; i++) {
        int c = tid + i * 256;
        o[c] = roundtf((v[i] - mean) * rstd * w[c] + b[c]);
    }
}

// ---------------- TF32 tensor-core GEMM (3-stage cp.async + A-ldmatrix, KT=32) ----------------
#define KT   32
#define SA   36
#define SROWB (SA * 4)     // 144 bytes per A smem row
#define SB   136           // stride%32==8 -> B frag banks 8*lc+lr all distinct
#define BSZ  (KT * SB)

template <int MT, bool BIAS, bool GELU, bool RESID, bool RNDOUT>
__global__ __launch_bounds__(256, 2) void tgemm_k(
    const float* __restrict__ A, const float* __restrict__ B,
    const float* __restrict__ bias, const float* __restrict__ resid,
    float* __restrict__ C, int M, int Nout, int ldB, int K) {
    extern __shared__ float smem[];

    constexpr int ROWS = 32 * MT;          // A rows per block
    constexpr int ASZ  = ROWS * SA;        // floats
    constexpr int STG  = ASZ + BSZ;        // floats per stage
    constexpr uint32_t STGB = STG * 4;     // bytes per stage
    constexpr int TPR  = 256 / ROWS;       // threads per A row
    constexpr int KCH  = 32 / TPR;         // k floats per thread
    constexpr int NCPA = KCH / 4;          // cp16 per thread for A

    int tid = threadIdx.x;
    int lane = tid & 31;
    int wid = tid >> 5;
    int warp_m = wid >> 2;             // 0..1
    int warp_n = wid & 3;              // 0..3
    int lr = lane >> 2;                // 0..7
    int lc = lane & 3;                 // 0..3

    int row0 = blockIdx.x * ROWS;      // row tile on FAST grid axis (L2 B reuse)
    int col0 = blockIdx.y * 128;

    int aM  = tid / TPR;               // A row in tile
    int aK4 = (tid % TPR) * KCH;       // A k base
    int bK  = tid >> 3;                // 0..31 (B row)
    int bN4 = (tid & 7) * 4;           // B n base (+u*32)

    float acc[MT][4][4];
    #pragma unroll
    for (int i = 0; i < MT; i++)
        #pragma unroll
        for (int j = 0; j < 4; j++)
            #pragma unroll
            for (int q = 0; q < 4; q++) acc[i][j][q] = 0.f;

    const float* aSrcBase = A + (size_t)(row0 + aM) * K + aK4;
    const float* bSrcBase = B + (size_t)bK * ldB + col0 + bN4;

    uint32_t smBase = (uint32_t)__cvta_generic_to_shared(smem);

    auto load_stage = [&](int kt, int s) {
        uint32_t base = smBase + (uint32_t)s * STGB;
        {
            uint32_t dst = base + (uint32_t)(aM * SA + aK4) * 4;
            const float* src = aSrcBase + kt;
            #pragma unroll
            for (int u = 0; u < NCPA; u++)
                cp16(dst + u * 16, src + u * 4);
        }
        {
            uint32_t dst = base + (uint32_t)(ASZ + bK * SB + bN4) * 4;
            const float* src = bSrcBase + (size_t)kt * ldB;
            #pragma unroll
            for (int u = 0; u < 4; u++)
                cp16(dst + u * 32 * 4, src + u * 32);
        }
    };

    uint32_t aLane = (uint32_t)((lane & 15) * SROWB + (lane >> 4) * 16);
    uint32_t aWarpOff = (uint32_t)(warp_m * (MT * 16) * SROWB);

    int nIter = K / KT;
    load_stage(0, 0);
    cp_commit();
    load_stage(KT, 1);
    cp_commit();

    for (int it = 0; it < nIter; it++) {
        if (it + 1 < nIter) cp_wait1(); else cp_wait0();
        __syncthreads();

        uint32_t stageBase = smBase + (uint32_t)(it % 3) * STGB;
        uint32_t aBase = stageBase + aWarpOff + aLane;
        const uint32_t* Bs = (const uint32_t*)smem + (size_t)(it % 3) * STG + ASZ;

        #pragma unroll
        for (int ks = 0; ks < 4; ks++) {
            int k0 = ks * 8;
            uint32_t af[MT][4];
            #pragma unroll
            for (int mt = 0; mt < MT; mt++)
                ldsm4(af[mt], aBase + (uint32_t)(mt * 16 * SROWB + ks * 32));
            #pragma unroll
            for (int nt = 0; nt < 4; nt++) {
                int bn = warp_n * 32 + nt * 8;
                uint32_t b0 = Bs[(k0 + lc    ) * SB + bn + lr];
                uint32_t b1 = Bs[(k0 + 4 + lc) * SB + bn + lr];
                #pragma unroll
                for (int mt = 0; mt < MT; mt++)
                    mma_tf32(acc[mt][nt], af[mt][0], af[mt][1], af[mt][2], af[mt][3], b0, b1);
            }
        }

        if (it + 2 < nIter) {
            load_stage((it + 2) * KT, (it + 2) % 3);
            cp_commit();
        }
    }

    // ---- epilogue ----
    #pragma unroll
    for (int mt = 0; mt < MT; mt++) {
        int rbase = row0 + warp_m * (MT * 16) + mt * 16 + lr;
        #pragma unroll
        for (int nt = 0; nt < 4; nt++) {
            int cbase = col0 + warp_n * 32 + nt * 8 + lc * 2;
            #pragma unroll
            for (int half = 0; half < 2; half++) {
                int r = rbase + half * 8;
                #pragma unroll
                for (int q = 0; q < 2; q++) {
                    int c = cbase + q;
                    if (c < Nout) {
                        float v = acc[mt][nt][half * 2 + q];
                        if (BIAS) v += bias[c];
                        if (GELU) v = gelu_f(v);
                        if (RESID) v += resid[(size_t)r * Nout + c];
                        if (RNDOUT) v = roundtf(v);
                        C[(size_t)r * Nout + c] = v;
                    }
                }
            }
        }
    }
}

#define GEMM_SMEM_BYTES(MT) (3 * ((32 * (MT)) * SA + BSZ) * 4)

// ---------------- TF32 GEMM, KT=64 variant (head): fewer barriers per FLOP ----------------
// Block 128x128, 3 stages, 1 block/SM (204KB smem), single sync per K-tile.
// Same accumulation order as KT=32 (k-steps sequential) -> numerics identical.
#define KT2   64
#define SA2   68           // 68%32=4 -> ldsm conflict-free
#define SROWB2 (SA2 * 4)   // 272 bytes per A smem row
#define SB2   136
#define ASZ2  (128 * SA2)
#define BSZ2  (KT2 * SB2)
#define STG2  (ASZ2 + BSZ2)
#define GEMM64_SMEM (3 * STG2 * 4)

__global__ __launch_bounds__(256, 1) void tgemm64_k(
    const float* __restrict__ A, const float* __restrict__ B,
    float* __restrict__ C, int Nout, int ldB, int K) {
    extern __shared__ float smem[];

    int tid = threadIdx.x;
    int lane = tid & 31;
    int wid = tid >> 5;
    int warp_m = wid >> 2;             // 0..1
    int warp_n = wid & 3;              // 0..3
    int lr = lane >> 2;                // 0..7
    int lc = lane & 3;                 // 0..3

    int row0 = blockIdx.x * 128;       // row tile on fast axis (L2 B reuse)
    int col0 = blockIdx.y * 128;

    // cp.async mappings: A 128 rows x 64 fl (2 thr/row, 8 cp16); B 64 rows x 128 fl (4 thr/row, 8 cp16)
    int aM  = tid >> 1;
    int aK4 = (tid & 1) * 32;
    int bK  = tid >> 2;                // 0..63
    int bN4 = (tid & 3) * 32;

    float acc[4][4][4];
    #pragma unroll
    for (int i = 0; i < 4; i++)
        #pragma unroll
        for (int j = 0; j < 4; j++)
            #pragma unroll
            for (int q = 0; q < 4; q++) acc[i][j][q] = 0.f;

    const float* aSrcBase = A + (size_t)(row0 + aM) * K + aK4;
    const float* bSrcBase = B + (size_t)bK * ldB + col0 + bN4;

    uint32_t smBase = (uint32_t)__cvta_generic_to_shared(smem);

    auto load_stage = [&](int kt, int s) {
        uint32_t base = smBase + (uint32_t)s * (STG2 * 4);
        {
            uint32_t dst = base + (uint32_t)(aM * SA2 + aK4) * 4;
            const float* src = aSrcBase + kt;
            #pragma unroll
            for (int u = 0; u < 8; u++)
                cp16(dst + u * 16, src + u * 4);
        }
        {
            uint32_t dst = base + (uint32_t)(ASZ2 + bK * SB2 + bN4) * 4;
            const float* src = bSrcBase + (size_t)kt * ldB;
            #pragma unroll
            for (int u = 0; u < 8; u++)
                cp16(dst + u * 16, src + u * 4);
        }
    };

    uint32_t aLane = (uint32_t)((lane & 15) * SROWB2 + (lane >> 4) * 16);
    uint32_t aWarpOff = (uint32_t)(warp_m * 64 * SROWB2);

    int nIter = K / KT2;
    load_stage(0, 0);
    cp_commit();
    load_stage(KT2, 1);
    cp_commit();

    for (int it = 0; it < nIter; it++) {
        if (it + 1 < nIter) cp_wait1(); else cp_wait0();
        __syncthreads();

        uint32_t stageBase = smBase + (uint32_t)(it % 3) * (STG2 * 4);
        uint32_t aBase = stageBase + aWarpOff + aLane;
        const uint32_t* Bs = (const uint32_t*)smem + (size_t)(it % 3) * STG2 + ASZ2;

        #pragma unroll
        for (int ks = 0; ks < 8; ks++) {
            int k0 = ks * 8;
            uint32_t af[4][4];
            #pragma unroll
            for (int mt = 0; mt < 4; mt++)
                ldsm4(af[mt], aBase + (uint32_t)(mt * 16 * SROWB2 + ks * 32));
            #pragma unroll
            for (int nt = 0; nt < 4; nt++) {
                int bn = warp_n * 32 + nt * 8;
                uint32_t b0 = Bs[(k0 + lc    ) * SB2 + bn + lr];
                uint32_t b1 = Bs[(k0 + 4 + lc) * SB2 + bn + lr];
                #pragma unroll
                for (int mt = 0; mt < 4; mt++)
                    mma_tf32(acc[mt][nt], af[mt][0], af[mt][1], af[mt][2], af[mt][3], b0, b1);
            }
        }

        if (it + 2 < nIter) {
            load_stage((it + 2) * KT2, (it + 2) % 3);
            cp_commit();
        }
    }

    // ---- epilogue (no bias/gelu/resid; guarded by Nout) ----
    #pragma unroll
    for (int mt = 0; mt < 4; mt++) {
        int rbase = row0 + warp_m * 64 + mt * 16 + lr;
        #pragma unroll
        for (int nt = 0; nt < 4; nt++) {
            int cbase = col0 + warp_n * 32 + nt * 8 + lc * 2;
            #pragma unroll
            for (int half = 0; half < 2; half++) {
                int r = rbase + half * 8;
                #pragma unroll
                for (int q = 0; q < 2; q++) {
                    int c = cbase + q;
                    if (c < Nout)
                        C[(size_t)r * Nout + c] = acc[mt][nt][half * 2 + q];
                }
            }
        }
    }
}

// ---------------- tensor-core flash attention ----------------
#define FSTR 68    // Q / K / P smem row stride (floats); 68%32=4 -> ldsm conflict-free
#define VSTR 72    // V smem row stride; 72%32=8 -> scalar B frag conflict-free
#define FLASH_SMEM ((2 * 64 * FSTR + 64 * VSTR) * 4)

__global__ __launch_bounds__(128) void flash_attn2_k(const float* __restrict__ qkv,
                                                     float* __restrict__ y) {
    extern __shared__ float fs[];
    float* Vsf = fs + 2 * 64 * FSTR;

    int bh = blockIdx.y;
    int b = bh / NH, h = bh % NH;
    int qt = (TT / 64 - 1) - (int)blockIdx.x;   // longest blocks first
    int t0 = qt * 64;
    int tid = threadIdx.x;
    int lane = tid & 31;
    int w = tid >> 5;
    int lr = lane >> 2, lc = lane & 3;

    uint32_t qsB = (uint32_t)__cvta_generic_to_shared(fs);
    uint32_t kpB = qsB + 64 * FSTR * 4;
    uint32_t vsB = kpB + 64 * FSTR * 4;

    int qr = tid >> 1;
    int qc = (tid & 1) * 32;

    // ---- load Q tile ----
    {
        const float* src = qkv + (size_t)(b * TT + t0 + qr) * (3 * CC) + h * HD + qc;
        uint32_t dst = qsB + (uint32_t)(qr * FSTR + qc) * 4;
        #pragma unroll
        for (int u = 0; u < 8; u++)
            cp16(dst + u * 16, src + u * 4);
        cp_commit(); cp_wait0();
    }
    __syncthreads();

    uint32_t qf[8][4];
    {
        uint32_t qa = qsB + (uint32_t)(w * 16 * FSTR * 4 + (lane & 15) * FSTR * 4 + (lane >> 4) * 16);
        #pragma unroll
        for (int ks = 0; ks < 8; ks++)
            ldsm4(qf[ks], qa + (uint32_t)(ks * 32));
    }

    float m_i[2] = {-1e30f, -1e30f};
    float l_i[2] = {0.f, 0.f};
    float acc[8][4];
    #pragma unroll
    for (int i = 0; i < 8; i++)
        #pragma unroll
        for (int j = 0; j < 4; j++) acc[i][j] = 0.f;

    uint32_t kb = kpB + (uint32_t)((((lane & 7) + ((lane >> 4) & 1) * 8) * FSTR) * 4 + ((lane >> 3) & 1) * 16);
    uint32_t pa = kpB + (uint32_t)(w * 16 * FSTR * 4 + (lane & 15) * FSTR * 4 + (lane >> 4) * 16);

    int nTiles = qt + 1;
    for (int st = 0; st < nTiles; st++) {
        int s0 = st * 64;

        __syncthreads();
        {
            const float* ksrc = qkv + (size_t)(b * TT + s0 + qr) * (3 * CC) + CC + h * HD + qc;
            uint32_t kdst = kpB + (uint32_t)(qr * FSTR + qc) * 4;
            #pragma unroll
            for (int u = 0; u < 8; u++)
                cp16(kdst + u * 16, ksrc + u * 4);
            const float* vsrc = qkv + (size_t)(b * TT + s0 + qr) * (3 * CC) + 2 * CC + h * HD + qc;
            uint32_t vdst = vsB + (uint32_t)(qr * VSTR + qc) * 4;
            #pragma unroll
            for (int u = 0; u < 8; u++)
                cp16(vdst + u * 16, vsrc + u * 4);
            cp_commit(); cp_wait0();
        }
        __syncthreads();

        float S[8][4];
        #pragma unroll
        for (int i = 0; i < 8; i++)
            #pragma unroll
            for (int j = 0; j < 4; j++) S[i][j] = 0.f;

        #pragma unroll
        for (int ks = 0; ks < 8; ks++) {
            #pragma unroll
            for (int ng = 0; ng < 4; ng++) {
                uint32_t bf[4];
                ldsm4(bf, kb + (uint32_t)(ng * 16 * FSTR * 4 + ks * 32));
                mma_tf32(S[ng * 2],     qf[ks][0], qf[ks][1], qf[ks][2], qf[ks][3], bf[0], bf[1]);
                mma_tf32(S[ng * 2 + 1], qf[ks][0], qf[ks][1], qf[ks][2], qf[ks][3], bf[2], bf[3]);
            }
        }

        const float scale = 0.125f;
        bool diag = (st == qt);
        #pragma unroll
        for (int half = 0; half < 2; half++) {
            int row = t0 + w * 16 + half * 8 + lr;
            float rmax = -1e30f;
            #pragma unroll
            for (int nt = 0; nt < 8; nt++) {
                #pragma unroll
                for (int q = 0; q < 2; q++) {
                    float v = S[nt][half * 2 + q] * scale;
                    if (diag && (s0 + nt * 8 + 2 * lc + q > row)) v = -1e30f;
                    S[nt][half * 2 + q] = v;
                    rmax = fmaxf(rmax, v);
                }
            }
            rmax = fmaxf(rmax, __shfl_xor_sync(0xffffffffu, rmax, 1));
            rmax = fmaxf(rmax, __shfl_xor_sync(0xffffffffu, rmax, 2));
            float mnew = fmaxf(m_i[half], rmax);
            float alpha = __expf(m_i[half] - mnew);
            float rsum = 0.f;
            #pragma unroll
            for (int nt = 0; nt < 8; nt++) {
                #pragma unroll
                for (int q = 0; q < 2; q++) {
                    float p = __expf(S[nt][half * 2 + q] - mnew);
                    S[nt][half * 2 + q] = p;
                    rsum += p;
                }
            }
            rsum += __shfl_xor_sync(0xffffffffu, rsum, 1);
            rsum += __shfl_xor_sync(0xffffffffu, rsum, 2);
            l_i[half] = l_i[half] * alpha + rsum;
            m_i[half] = mnew;
            #pragma unroll
            for (int nt = 0; nt < 8; nt++) {
                acc[nt][half * 2]     *= alpha;
                acc[nt][half * 2 + 1] *= alpha;
            }
        }

        __syncthreads();

        {
            float* Ps = fs + 64 * FSTR;
            #pragma unroll
            for (int half = 0; half < 2; half++) {
                int r = w * 16 + half * 8 + lr;
                #pragma unroll
                for (int nt = 0; nt < 8; nt++) {
                    float2 pv;
                    pv.x = roundtf(S[nt][half * 2]);
                    pv.y = roundtf(S[nt][half * 2 + 1]);
                    *(float2*)&Ps[r * FSTR + nt * 8 + 2 * lc] = pv;
                }
            }
        }
        __syncwarp();

        #pragma unroll
        for (int ks = 0; ks < 8; ks++) {
            uint32_t pf[4];
            ldsm4(pf, pa + (uint32_t)(ks * 32));
            int k0 = ks * 8;
            #pragma unroll
            for (int nt = 0; nt < 8; nt++) {
                uint32_t b0 = __float_as_uint(Vsf[(k0 + lc    ) * VSTR + nt * 8 + lr]);
                uint32_t b1 = __float_as_uint(Vsf[(k0 + 4 + lc) * VSTR + nt * 8 + lr]);
                mma_tf32(acc[nt], pf[0], pf[1], pf[2], pf[3], b0, b1);
            }
        }
    }

    #pragma unroll
    for (int half = 0; half < 2; half++) {
        float inv = 1.f / l_i[half];
        int t = t0 + w * 16 + half * 8 + lr;
        float* orow = y + (size_t)(b * TT + t) * CC + h * HD;
        #pragma unroll
        for (int nt = 0; nt < 8; nt++) {
            float2 ov;
            ov.x = roundtf(acc[nt][half * 2]     * inv);
            ov.y = roundtf(acc[nt][half * 2 + 1] * inv);
            *(float2*)&orow[nt * 8 + 2 * lc] = ov;
        }
    }
}

// ---------------- host launcher ----------------
extern "C" void kernel_launch(void* const* d_in, const int* in_sizes, int n_in,
                              void* d_out, int out_size) {
    (void)in_sizes; (void)n_in; (void)out_size;
    const int*   idx    = (const int*)  d_in[0];
    const float* wte    = (const float*)d_in[1];
    const float* wpe    = (const float*)d_in[2];
    const float* ln1_w  = (const float*)d_in[3];
    const float* ln1_b  = (const float*)d_in[4];
    const float* qkv_w  = (const float*)d_in[5];
    const float* qkv_b  = (const float*)d_in[6];
    const float* proj_w = (const float*)d_in[7];
    const float* proj_b = (const float*)d_in[8];
    const float* ln2_w  = (const float*)d_in[9];
    const float* ln2_b  = (const float*)d_in[10];
    const float* fc_w   = (const float*)d_in[11];
    const float* fc_b   = (const float*)d_in[12];
    const float* fc2_w  = (const float*)d_in[13];
    const float* fc2_b  = (const float*)d_in[14];
    const float* lnf_w  = (const float*)d_in[15];
    const float* lnf_b  = (const float*)d_in[16];
    const float* head_w = (const float*)d_in[17];
    float* out = (float*)d_out;

    float *x, *h, *qkv, *y, *m1, *wpad, *wr;
    cudaGetSymbolAddress((void**)&x,    g_x);
    cudaGetSymbolAddress((void**)&h,    g_h);
    cudaGetSymbolAddress((void**)&qkv,  g_qkv);
    cudaGetSymbolAddress((void**)&y,    g_y);
    cudaGetSymbolAddress((void**)&m1,   g_m1);
    cudaGetSymbolAddress((void**)&wpad, g_wpad);
    cudaGetSymbolAddress((void**)&wr,   g_wr);

    cudaFuncSetAttribute(tgemm_k<4, true,  false, false, true >, cudaFuncAttributeMaxDynamicSharedMemorySize, GEMM_SMEM_BYTES(4));
    cudaFuncSetAttribute(tgemm_k<4, true,  true,  false, true >, cudaFuncAttributeMaxDynamicSharedMemorySize, GEMM_SMEM_BYTES(4));
    cudaFuncSetAttribute(tgemm_k<2, true,  false, true,  false>, cudaFuncAttributeMaxDynamicSharedMemorySize, GEMM_SMEM_BYTES(2));
    cudaFuncSetAttribute(tgemm64_k, cudaFuncAttributeMaxDynamicSharedMemorySize, GEMM64_SMEM);
    cudaFuncSetAttribute(flash_attn2_k, cudaFuncAttributeMaxDynamicSharedMemorySize, FLASH_SMEM);

    float* wr_qkv  = wr + OFF_QKV;
    float* wr_proj = wr + OFF_PROJ;
    float* wr_fc   = wr + OFF_FC;
    float* wr_fc2  = wr + OFF_FC2;

    {
        int blocks = (int)((P_S4 + 255) / 256);
        prep_k<<<blocks, 256>>>(qkv_w, proj_w, fc_w, fc2_w, head_w, wr, wpad);
    }

    embed_k<<<NTOK, 256>>>(idx, wte, wpe, x);

    for (int l = 0; l < LL; l++) {
        const float* l_ln1w  = ln1_w  + (size_t)l * CC;
        const float* l_ln1b  = ln1_b  + (size_t)l * CC;
        const float* l_qkvw  = wr_qkv  + (size_t)l * CC * 3 * CC;
        const float* l_qkvb  = qkv_b  + (size_t)l * 3 * CC;
        const float* l_pw    = wr_proj + (size_t)l * CC * CC;
        const float* l_pb    = proj_b + (size_t)l * CC;
        const float* l_ln2w  = ln2_w  + (size_t)l * CC;
        const float* l_ln2b  = ln2_b  + (size_t)l * CC;
        const float* l_fcw   = wr_fc   + (size_t)l * CC * 4 * CC;
        const float* l_fcb   = fc_b   + (size_t)l * 4 * CC;
        const float* l_fc2w  = wr_fc2  + (size_t)l * 4 * CC * CC;
        const float* l_fc2b  = fc2_b  + (size_t)l * CC;

        layernorm_k<<<NTOK, 256>>>(x, l_ln1w, l_ln1b, h);
        tgemm_k<4, true, false, false, true><<<dim3(NTOK / 128, (3 * CC) / 128), 256, GEMM_SMEM_BYTES(4)>>>(
            h, l_qkvw, l_qkvb, nullptr, qkv, NTOK, 3 * CC, 3 * CC, CC);
        flash_attn2_k<<<dim3(TT / 64, BH), 128, FLASH_SMEM>>>(qkv, y);
        tgemm_k<2, true, false, true, false><<<dim3(NTOK / 64, CC / 128), 256, GEMM_SMEM_BYTES(2)>>>(
            y, l_pw, l_pb, x, x, NTOK, CC, CC, CC);
        layernorm_k<<<NTOK, 256>>>(x, l_ln2w, l_ln2b, h);
        tgemm_k<4, true, true, false, true><<<dim3(NTOK / 128, (4 * CC) / 128), 256, GEMM_SMEM_BYTES(4)>>>(
            h, l_fcw, l_fcb, nullptr, m1, NTOK, 4 * CC, 4 * CC, CC);
        tgemm_k<2, true, false, true, false><<<dim3(NTOK / 64, CC / 128), 256, GEMM_SMEM_BYTES(2)>>>(
            m1, l_fc2w, l_fc2b, x, x, NTOK, CC, CC, 4 * CC);
    }

    layernorm_k<<<NTOK, 256>>>(x, lnf_w, lnf_b, h);
    tgemm64_k<<<dim3(NTOK / 128, NPAD / 128), 256, GEMM64_SMEM>>>(
        h, wpad, out, VV, NPAD, CC);
}